// round 2
// baseline (speedup 1.0000x reference)
#include <cuda_runtime.h>

#define BATCH 2048
#define T 128
#define NS 16
#define MS 8
#define CS 4
#define DT 0.01f
#define WB 4   // warps (batches) per forward block

// Scratch: smoother gain transpose X_t = G_t^T (t = 0..T-2), and predicted states.
__device__ float g_X[(size_t)(T - 1) * BATCH * NS * NS];   // ~266 MB
__device__ float g_sp[(size_t)BATCH * T * NS];             // ~16 MB

__device__ __forceinline__ float4 ld4(const float* p) { return *reinterpret_cast<const float4*>(p); }
__device__ __forceinline__ void st4(float* p, float4 v) { *reinterpret_cast<float4*>(p) = v; }

__device__ __forceinline__ void fma8(float a, float4 b0, float4 b1, float acc[8]) {
    acc[0] = fmaf(a, b0.x, acc[0]); acc[1] = fmaf(a, b0.y, acc[1]);
    acc[2] = fmaf(a, b0.z, acc[2]); acc[3] = fmaf(a, b0.w, acc[3]);
    acc[4] = fmaf(a, b1.x, acc[4]); acc[5] = fmaf(a, b1.y, acc[5]);
    acc[6] = fmaf(a, b1.z, acc[6]); acc[7] = fmaf(a, b1.w, acc[7]);
}

__global__ __launch_bounds__(WB * 32) void kf_forward(
    const float* __restrict__ state0, const float* __restrict__ P0,
    const float* __restrict__ controls, const float* __restrict__ obs,
    const float* __restrict__ A, const float* __restrict__ Bc,
    const float* __restrict__ H, const float* __restrict__ Q,
    const float* __restrict__ R, float* __restrict__ sf_out)
{
    // Block-shared constants (stride 20 -> 16B-aligned rows, low bank conflicts)
    __shared__ float Fb[16 * 20], Ftb[16 * 20], Ab[16 * 20], Qb[16 * 20];
    __shared__ float Hb[8 * 20], Ht[16 * 8], Rb[64], Bcb[64];
    // Per-warp (per-batch) working set
    __shared__ float Pm[WB][16 * 20], Wm[WB][16 * 20], PPm[WB][16 * 20];
    __shared__ float PHtm[WB][16 * 8], SAm[WB][8 * 25], X2m[WB][8 * 17], HPm[WB][8 * 20];
    __shared__ float svm[WB][16], spm[WB][16], ivm[WB][8];

    const int tid = threadIdx.x;
    for (int idx = tid; idx < 256; idx += WB * 32) {
        int i = idx >> 4, k = idx & 15;
        float a = A[idx];
        float f = (i == k ? 1.0f : 0.0f) + DT * a;
        Ab[i * 20 + k] = a; Fb[i * 20 + k] = f; Ftb[k * 20 + i] = f;
        Qb[i * 20 + k] = Q[idx];
    }
    for (int idx = tid; idx < 128; idx += WB * 32) {
        int q = idx >> 4, k = idx & 15;
        float h = H[idx];
        Hb[q * 20 + k] = h; Ht[k * 8 + q] = h;
    }
    if (tid < 64) { Rb[tid] = R[tid]; Bcb[tid] = Bc[tid]; }
    __syncthreads();

    const int w = tid >> 5, lane = tid & 31;
    const int b = blockIdx.x * WB + w;
    float* P  = Pm[w];  float* W  = Wm[w];  float* PP = PPm[w];
    float* PHt = PHtm[w]; float* SA = SAm[w]; float* X2 = X2m[w]; float* HP = HPm[w];
    float* sv = svm[w]; float* sp = spm[w]; float* iv = ivm[w];

    const int row = lane >> 1, half = lane & 1, j0 = half * 8;
    const int r4 = lane >> 2, q4 = lane & 3;

    // init carry
    for (int idx = lane; idx < 256; idx += 32)
        P[(idx >> 4) * 20 + (idx & 15)] = P0[(size_t)b * 256 + idx];
    if (lane < 16) sv[lane] = state0[b * 16 + lane];
    __syncwarp();

    for (int t = 0; t < T; ++t) {
        // ---- Phase 1: W = F * P  (F * P_f[t-1]) ----
        {
            float acc[8];
            #pragma unroll
            for (int j = 0; j < 8; ++j) acc[j] = 0.0f;
            #pragma unroll
            for (int k = 0; k < 16; ++k) {
                float a = Fb[row * 20 + k];
                fma8(a, ld4(&P[k * 20 + j0]), ld4(&P[k * 20 + j0 + 4]), acc);
            }
            st4(&W[row * 20 + j0],     make_float4(acc[0], acc[1], acc[2], acc[3]));
            st4(&W[row * 20 + j0 + 4], make_float4(acc[4], acc[5], acc[6], acc[7]));
        }
        __syncwarp();

        // ---- Phase 2: PP = W * F^T + Q ----
        {
            float acc[8];
            float4 q0 = ld4(&Qb[row * 20 + j0]);
            float4 q1 = ld4(&Qb[row * 20 + j0 + 4]);
            acc[0] = q0.x; acc[1] = q0.y; acc[2] = q0.z; acc[3] = q0.w;
            acc[4] = q1.x; acc[5] = q1.y; acc[6] = q1.z; acc[7] = q1.w;
            #pragma unroll
            for (int k = 0; k < 16; ++k) {
                float a = W[row * 20 + k];
                fma8(a, ld4(&Ftb[k * 20 + j0]), ld4(&Ftb[k * 20 + j0 + 4]), acc);
            }
            st4(&PP[row * 20 + j0],     make_float4(acc[0], acc[1], acc[2], acc[3]));
            st4(&PP[row * 20 + j0 + 4], make_float4(acc[4], acc[5], acc[6], acc[7]));
        }
        __syncwarp();

        // ---- Phase 3: PHt[i][q] = sum_k PP[i][k] * H[q][k] ----
        {
            const int qh = half * 4;
            float4 acc = make_float4(0.f, 0.f, 0.f, 0.f);
            #pragma unroll
            for (int k = 0; k < 16; ++k) {
                float p = PP[row * 20 + k];
                float4 h = ld4(&Ht[k * 8 + qh]);
                acc.x = fmaf(p, h.x, acc.x); acc.y = fmaf(p, h.y, acc.y);
                acc.z = fmaf(p, h.z, acc.z); acc.w = fmaf(p, h.w, acc.w);
            }
            st4(&PHt[row * 8 + qh], acc);
        }
        __syncwarp();

        // ---- Phase 4: SA = [S | PHt^T],  S = H*PHt + R ----
        {
            const int a = r4, b2 = q4 * 2;
            float s0 = Rb[a * 8 + b2], s1 = Rb[a * 8 + b2 + 1];
            #pragma unroll
            for (int k = 0; k < 16; ++k) {
                float h = Hb[a * 20 + k];
                s0 = fmaf(h, PHt[k * 8 + b2], s0);
                s1 = fmaf(h, PHt[k * 8 + b2 + 1], s1);
            }
            SA[a * 25 + b2] = s0; SA[a * 25 + b2 + 1] = s1;
            const int qh = half * 4;
            #pragma unroll
            for (int q = 0; q < 4; ++q)
                SA[(qh + q) * 25 + 8 + row] = PHt[row * 8 + qh + q];
        }
        __syncwarp();

        // ---- Phase 5: GJ solve S * X2 = PHt^T  (8x8, SPD, no pivot) ----
        {
            const int r = r4, c0 = q4 * 6;
            #pragma unroll 1
            for (int p = 0; p < 8; ++p) {
                float invp = 1.0f / SA[p * 25 + p];
                float f = SA[r * 25 + p] * invp;
                float pr[6];
                #pragma unroll
                for (int c = 0; c < 6; ++c) pr[c] = SA[p * 25 + c0 + c];
                __syncwarp();
                if (r != p) {
                    #pragma unroll
                    for (int c = 0; c < 6; ++c)
                        SA[r * 25 + c0 + c] -= f * pr[c];
                }
                __syncwarp();
            }
            float invd = 1.0f / SA[r * 25 + r];
            #pragma unroll
            for (int c = 0; c < 4; ++c)
                X2[r * 17 + q4 * 4 + c] = SA[r * 25 + 8 + q4 * 4 + c] * invd;
        }
        __syncwarp();

        // ---- Phase 6: state prediction + update ----
        {
            const float* u = &controls[((size_t)b * T + t) * CS];
            const float* y = &obs[((size_t)b * T + t) * MS];
            if (lane < 16) {
                float acc = 0.0f;
                #pragma unroll
                for (int k = 0; k < 16; ++k) acc = fmaf(Ab[lane * 20 + k], sv[k], acc);
                #pragma unroll
                for (int c = 0; c < 4; ++c) acc = fmaf(Bcb[lane * 4 + c], u[c], acc);
                float spv = sv[lane] + DT * acc;
                sp[lane] = spv;
                if (t > 0) g_sp[((size_t)b * T + t) * NS + lane] = spv;
            }
            __syncwarp();
            if (lane < 8) {
                float acc = y[lane];
                #pragma unroll
                for (int k = 0; k < 16; ++k) acc = fmaf(-Hb[lane * 20 + k], sp[k], acc);
                iv[lane] = acc;
            }
            __syncwarp();
            if (lane < 16) {
                float acc = sp[lane];
                #pragma unroll
                for (int q = 0; q < 8; ++q) acc = fmaf(X2[q * 17 + lane], iv[q], acc);
                sv[lane] = acc;
                sf_out[((size_t)b * T + t) * NS + lane] = acc;
            }
            __syncwarp();
        }

        // ---- Phase 7: HP[q][j] = sum_k H[q][k] * PP[k][j] ----
        {
            const int q = r4, jh = q4 * 4;
            float4 acc = make_float4(0.f, 0.f, 0.f, 0.f);
            #pragma unroll
            for (int k = 0; k < 16; ++k) {
                float h = Hb[q * 20 + k];
                float4 pp = ld4(&PP[k * 20 + jh]);
                acc.x = fmaf(h, pp.x, acc.x); acc.y = fmaf(h, pp.y, acc.y);
                acc.z = fmaf(h, pp.z, acc.z); acc.w = fmaf(h, pp.w, acc.w);
            }
            st4(&HP[q * 20 + jh], acc);
        }
        __syncwarp();

        // ---- Phase 8: P_new = PP - K * HP  (K[i][q] = X2[q][i]) ----
        {
            float4 a0 = ld4(&PP[row * 20 + j0]);
            float4 a1 = ld4(&PP[row * 20 + j0 + 4]);
            #pragma unroll
            for (int q = 0; q < 8; ++q) {
                float x = X2[q * 17 + row];
                float4 h0 = ld4(&HP[q * 20 + j0]);
                float4 h1 = ld4(&HP[q * 20 + j0 + 4]);
                a0.x = fmaf(-x, h0.x, a0.x); a0.y = fmaf(-x, h0.y, a0.y);
                a0.z = fmaf(-x, h0.z, a0.z); a0.w = fmaf(-x, h0.w, a0.w);
                a1.x = fmaf(-x, h1.x, a1.x); a1.y = fmaf(-x, h1.y, a1.y);
                a1.z = fmaf(-x, h1.z, a1.z); a1.w = fmaf(-x, h1.w, a1.w);
            }
            st4(&P[row * 20 + j0], a0);
            st4(&P[row * 20 + j0 + 4], a1);
        }
        __syncwarp();

        // ---- Phase 9: smoother gain: solve PP * X = W, X = G_{t-1}^T ----
        if (t > 0) {
            #pragma unroll 1
            for (int p = 0; p < 16; ++p) {
                float invp = 1.0f / PP[p * 20 + p];
                float f = PP[row * 20 + p] * invp;
                float4 pa0 = ld4(&PP[p * 20 + j0]);
                float4 pa1 = ld4(&PP[p * 20 + j0 + 4]);
                float4 pw0 = ld4(&W[p * 20 + j0]);
                float4 pw1 = ld4(&W[p * 20 + j0 + 4]);
                __syncwarp();
                if (row != p) {
                    float4 a0 = ld4(&PP[row * 20 + j0]);
                    float4 a1 = ld4(&PP[row * 20 + j0 + 4]);
                    float4 w0 = ld4(&W[row * 20 + j0]);
                    float4 w1 = ld4(&W[row * 20 + j0 + 4]);
                    a0.x = fmaf(-f, pa0.x, a0.x); a0.y = fmaf(-f, pa0.y, a0.y);
                    a0.z = fmaf(-f, pa0.z, a0.z); a0.w = fmaf(-f, pa0.w, a0.w);
                    a1.x = fmaf(-f, pa1.x, a1.x); a1.y = fmaf(-f, pa1.y, a1.y);
                    a1.z = fmaf(-f, pa1.z, a1.z); a1.w = fmaf(-f, pa1.w, a1.w);
                    w0.x = fmaf(-f, pw0.x, w0.x); w0.y = fmaf(-f, pw0.y, w0.y);
                    w0.z = fmaf(-f, pw0.z, w0.z); w0.w = fmaf(-f, pw0.w, w0.w);
                    w1.x = fmaf(-f, pw1.x, w1.x); w1.y = fmaf(-f, pw1.y, w1.y);
                    w1.z = fmaf(-f, pw1.z, w1.z); w1.w = fmaf(-f, pw1.w, w1.w);
                    st4(&PP[row * 20 + j0], a0);
                    st4(&PP[row * 20 + j0 + 4], a1);
                    st4(&W[row * 20 + j0], w0);
                    st4(&W[row * 20 + j0 + 4], w1);
                }
                __syncwarp();
            }
            float invd = 1.0f / PP[row * 20 + row];
            float* xo = &g_X[(((size_t)(t - 1) * BATCH + b) * 256) + row * 16 + j0];
            float4 x0 = ld4(&W[row * 20 + j0]);
            float4 x1 = ld4(&W[row * 20 + j0 + 4]);
            x0.x *= invd; x0.y *= invd; x0.z *= invd; x0.w *= invd;
            x1.x *= invd; x1.y *= invd; x1.z *= invd; x1.w *= invd;
            st4(xo, x0);
            st4(xo + 4, x1);
        }
        __syncwarp();
    }
}

__global__ __launch_bounds__(256) void kf_backward(float* __restrict__ out)
{
    const int warp = (blockIdx.x * blockDim.x + threadIdx.x) >> 5;
    const int lane = threadIdx.x & 31;
    const int b = warp;
    const int i = lane & 15;   // both half-warps duplicate -> safe full-warp shfl

    float ss = out[((size_t)b * T + (T - 1)) * NS + i];
    #pragma unroll 1
    for (int t = T - 2; t >= 0; --t) {
        float spn = g_sp[((size_t)b * T + t + 1) * NS + i];
        float d = ss - spn;
        float acc = out[((size_t)b * T + t) * NS + i];   // s_f[t]
        const float* Xp = &g_X[((size_t)t * BATCH + b) * 256];
        #pragma unroll
        for (int j = 0; j < 16; ++j) {
            float dj = __shfl_sync(0xffffffffu, d, j, 16);
            acc = fmaf(dj, Xp[j * 16 + i], acc);
        }
        ss = acc;
        if (lane < 16) out[((size_t)b * T + t) * NS + i] = ss;
    }
}

extern "C" void kernel_launch(void* const* d_in, const int* in_sizes, int n_in,
                              void* d_out, int out_size) {
    (void)in_sizes; (void)n_in; (void)out_size;
    const float* state0   = (const float*)d_in[0];
    const float* P0       = (const float*)d_in[1];
    const float* controls = (const float*)d_in[2];
    const float* obs      = (const float*)d_in[3];
    const float* A        = (const float*)d_in[4];
    const float* Bc       = (const float*)d_in[5];
    const float* H        = (const float*)d_in[6];
    const float* Q        = (const float*)d_in[7];
    const float* R        = (const float*)d_in[8];
    float* out = (float*)d_out;

    kf_forward<<<BATCH / WB, WB * 32>>>(state0, P0, controls, obs, A, Bc, H, Q, R, out);
    kf_backward<<<BATCH / 8, 256>>>(out);
}

// round 4
// speedup vs baseline: 1.9737x; 1.9737x over previous
#include <cuda_runtime.h>

#define BATCH 2048
#define T 128
#define NS 16
#define MS 8
#define CS 4
#define DT 0.01f
#define WB 2   // warps (batches) per forward block

// Scratch: smoother gain transpose X_t = G_t^T (t = 0..T-2), and predicted states.
__device__ float g_X[(size_t)(T - 1) * BATCH * NS * NS];   // ~266 MB
__device__ float g_sp[(size_t)BATCH * T * NS];             // ~16 MB

__device__ __forceinline__ float4 ld4(const float* p) { return *reinterpret_cast<const float4*>(p); }
__device__ __forceinline__ void st4(float* p, float4 v) { *reinterpret_cast<float4*>(p) = v; }
__device__ __forceinline__ float rcpa(float x) { float y; asm("rcp.approx.f32 %0, %1;" : "=f"(y) : "f"(x)); return y; }
__device__ __forceinline__ float shfl(float v, int s) { return __shfl_sync(0xffffffffu, v, s); }
__device__ __forceinline__ float shflx(float v, int m) { return __shfl_xor_sync(0xffffffffu, v, m); }

__global__ __launch_bounds__(WB * 32) void kf_forward(
    const float* __restrict__ state0, const float* __restrict__ P0,
    const float* __restrict__ controls, const float* __restrict__ obs,
    const float* __restrict__ A, const float* __restrict__ Bc,
    const float* __restrict__ H, const float* __restrict__ Q,
    const float* __restrict__ R, float* __restrict__ sf_out)
{
    __shared__ float Fb[16 * 20], Ftb[16 * 20], Ab[16 * 20], Qb[16 * 20];
    __shared__ float Hb[8 * 20], Ht[16 * 8], Rb[64], Bcb[64];
    __shared__ float Pm[WB][16 * 20], PPm[WB][16 * 20];
    __shared__ float PHtm[WB][16 * 8], X2m[WB][8 * 20], HPm[WB][8 * 20];
    __shared__ float svm[WB][16], spm[WB][16], ivm[WB][8];

    const int tid = threadIdx.x;
    for (int idx = tid; idx < 256; idx += WB * 32) {
        int i = idx >> 4, k = idx & 15;
        float a = A[idx];
        float f = (i == k ? 1.0f : 0.0f) + DT * a;
        Ab[i * 20 + k] = a; Fb[i * 20 + k] = f; Ftb[k * 20 + i] = f;
        Qb[i * 20 + k] = Q[idx];
    }
    for (int idx = tid; idx < 128; idx += WB * 32) {
        int q = idx >> 4, k = idx & 15;
        float h = H[idx];
        Hb[q * 20 + k] = h; Ht[k * 8 + q] = h;
    }
    if (tid < 64) { Rb[tid] = R[tid]; Bcb[tid] = Bc[tid]; }
    __syncthreads();

    const int wrp = tid >> 5, lane = tid & 31;
    const int b = blockIdx.x * WB + wrp;
    float* P  = Pm[wrp]; float* PP = PPm[wrp];
    float* PHt = PHtm[wrp]; float* X2 = X2m[wrp]; float* HP = HPm[wrp];
    float* sv = svm[wrp]; float* sp = spm[wrp]; float* iv = ivm[wrp];

    const int row = lane >> 1, h = lane & 1, j0 = h * 8;
    const int rr = row & 7;          // 8x8-solve row (lanes 16-31 duplicate, results discarded)
    const int q7 = lane >> 2, jh = (lane & 3) * 4;

    // init carry
    for (int idx = lane; idx < 256; idx += 32)
        P[(idx >> 4) * 20 + (idx & 15)] = P0[(size_t)b * 256 + idx];
    if (lane < 16) sv[lane] = state0[b * 16 + lane];

    // time-invariant per-lane rows
    float frow[16];
    #pragma unroll
    for (int k = 0; k < 16; ++k) frow[k] = Fb[row * 20 + k];
    __syncwarp();

    float a[8], w[8];   // PP row slice / W row slice (cols j0..j0+7)

    for (int t = 0; t < T; ++t) {
        // ---- Phase 1: W row = F * P  (P in LDS, result in regs) ----
        {
            #pragma unroll
            for (int j = 0; j < 8; ++j) w[j] = 0.0f;
            #pragma unroll
            for (int k = 0; k < 16; ++k) {
                float fv = frow[k];
                float4 p0 = ld4(&P[k * 20 + j0]);
                float4 p1 = ld4(&P[k * 20 + j0 + 4]);
                w[0] = fmaf(fv, p0.x, w[0]); w[1] = fmaf(fv, p0.y, w[1]);
                w[2] = fmaf(fv, p0.z, w[2]); w[3] = fmaf(fv, p0.w, w[3]);
                w[4] = fmaf(fv, p1.x, w[4]); w[5] = fmaf(fv, p1.y, w[5]);
                w[6] = fmaf(fv, p1.z, w[6]); w[7] = fmaf(fv, p1.w, w[7]);
            }
        }

        // ---- Phase 2: PP row = W * F^T + Q (regs; mirror to LDS for Phase 7) ----
        {
            float wk[16];
            #pragma unroll
            for (int j = 0; j < 8; ++j) {
                wk[j0 + j] = w[j];
                wk[(j0 ^ 8) + j] = shflx(w[j], 1);
            }
            float4 q0 = ld4(&Qb[row * 20 + j0]);
            float4 q1 = ld4(&Qb[row * 20 + j0 + 4]);
            a[0] = q0.x; a[1] = q0.y; a[2] = q0.z; a[3] = q0.w;
            a[4] = q1.x; a[5] = q1.y; a[6] = q1.z; a[7] = q1.w;
            #pragma unroll
            for (int k = 0; k < 16; ++k) {
                float wv = wk[k];
                float4 f0 = ld4(&Ftb[k * 20 + j0]);
                float4 f1 = ld4(&Ftb[k * 20 + j0 + 4]);
                a[0] = fmaf(wv, f0.x, a[0]); a[1] = fmaf(wv, f0.y, a[1]);
                a[2] = fmaf(wv, f0.z, a[2]); a[3] = fmaf(wv, f0.w, a[3]);
                a[4] = fmaf(wv, f1.x, a[4]); a[5] = fmaf(wv, f1.y, a[5]);
                a[6] = fmaf(wv, f1.z, a[6]); a[7] = fmaf(wv, f1.w, a[7]);
            }
            st4(&PP[row * 20 + j0],     make_float4(a[0], a[1], a[2], a[3]));
            st4(&PP[row * 20 + j0 + 4], make_float4(a[4], a[5], a[6], a[7]));
        }

        // ---- Phase 3: PHt[row][qh..qh+3] = sum_k PP[row][k] * H^T[k][q] ----
        {
            float pk[16];
            #pragma unroll
            for (int j = 0; j < 8; ++j) {
                pk[j0 + j] = a[j];
                pk[(j0 ^ 8) + j] = shflx(a[j], 1);
            }
            const int qh = h * 4;
            float4 acc = make_float4(0.f, 0.f, 0.f, 0.f);
            #pragma unroll
            for (int k = 0; k < 16; ++k) {
                float p = pk[k];
                float4 hv = ld4(&Ht[k * 8 + qh]);
                acc.x = fmaf(p, hv.x, acc.x); acc.y = fmaf(p, hv.y, acc.y);
                acc.z = fmaf(p, hv.z, acc.z); acc.w = fmaf(p, hv.w, acc.w);
            }
            st4(&PHt[row * 8 + qh], acc);
        }
        __syncwarp();

        // ---- Phase 4: S rows + RHS rows into registers ----
        // lane pair (2r, 2r+1) owns row r (r=0..7): h=0 -> S cols 0-3, RHS cols 0-7
        //                                           h=1 -> S cols 4-7, RHS cols 8-15
        float s4[4], rhs[8];
        {
            const int ch = h * 4;
            s4[0] = Rb[rr * 8 + ch];     s4[1] = Rb[rr * 8 + ch + 1];
            s4[2] = Rb[rr * 8 + ch + 2]; s4[3] = Rb[rr * 8 + ch + 3];
            #pragma unroll
            for (int k = 0; k < 16; ++k) {
                float hv = Hb[rr * 20 + k];
                float4 ph = ld4(&PHt[k * 8 + ch]);
                s4[0] = fmaf(hv, ph.x, s4[0]); s4[1] = fmaf(hv, ph.y, s4[1]);
                s4[2] = fmaf(hv, ph.z, s4[2]); s4[3] = fmaf(hv, ph.w, s4[3]);
            }
            #pragma unroll
            for (int j = 0; j < 8; ++j)
                rhs[j] = PHt[(h * 8 + j) * 8 + rr];   // RHS[r][i] = PHt[i][r]
        }

        // ---- Phase 5: GJ solve S * X2 = PHt^T (8x8), registers + shfl ----
        {
            #pragma unroll
            for (int p = 0; p < 8; ++p) {
                const int hp = (p >= 4) ? 1 : 0;
                float cand = s4[p & 3];
                float f_num = shfl(cand, (rr << 1) | hp);
                float diag  = shfl(cand, (p << 1) | hp);
                const int src = (p << 1) | h;
                float ps0 = shfl(s4[0], src), ps1 = shfl(s4[1], src);
                float ps2 = shfl(s4[2], src), ps3 = shfl(s4[3], src);
                float pr[8];
                #pragma unroll
                for (int j = 0; j < 8; ++j) pr[j] = shfl(rhs[j], src);
                float f = (rr == p) ? 0.0f : f_num * rcpa(diag);
                s4[0] = fmaf(-f, ps0, s4[0]); s4[1] = fmaf(-f, ps1, s4[1]);
                s4[2] = fmaf(-f, ps2, s4[2]); s4[3] = fmaf(-f, ps3, s4[3]);
                #pragma unroll
                for (int j = 0; j < 8; ++j) rhs[j] = fmaf(-f, pr[j], rhs[j]);
            }
            // divide by own diagonal S[r][r]
            float s01 = (rr & 1) ? s4[1] : s4[0];
            float s23 = (rr & 1) ? s4[3] : s4[2];
            float cand_r = (rr & 2) ? s23 : s01;
            float diag_r = shfl(cand_r, (rr << 1) | ((rr >= 4) ? 1 : 0));
            float invd = rcpa(diag_r);
            if (lane < 16) {
                st4(&X2[rr * 20 + h * 8],
                    make_float4(rhs[0] * invd, rhs[1] * invd, rhs[2] * invd, rhs[3] * invd));
                st4(&X2[rr * 20 + h * 8 + 4],
                    make_float4(rhs[4] * invd, rhs[5] * invd, rhs[6] * invd, rhs[7] * invd));
            }
        }
        __syncwarp();

        // ---- Phase 6: state prediction + update ----
        {
            const float* u = &controls[((size_t)b * T + t) * CS];
            const float* y = &obs[((size_t)b * T + t) * MS];
            if (lane < 16) {
                float acc = 0.0f;
                #pragma unroll
                for (int k = 0; k < 16; ++k) acc = fmaf(Ab[lane * 20 + k], sv[k], acc);
                #pragma unroll
                for (int c = 0; c < 4; ++c) acc = fmaf(Bcb[lane * 4 + c], u[c], acc);
                float spv = sv[lane] + DT * acc;
                sp[lane] = spv;
                if (t > 0) g_sp[((size_t)b * T + t) * NS + lane] = spv;
            }
            __syncwarp();
            if (lane < 8) {
                float acc = y[lane];
                #pragma unroll
                for (int k = 0; k < 16; ++k) acc = fmaf(-Hb[lane * 20 + k], sp[k], acc);
                iv[lane] = acc;
            }
            __syncwarp();
            if (lane < 16) {
                float acc = sp[lane];
                #pragma unroll
                for (int q = 0; q < 8; ++q) acc = fmaf(X2[q * 20 + lane], iv[q], acc);
                sv[lane] = acc;
                sf_out[((size_t)b * T + t) * NS + lane] = acc;
            }
            __syncwarp();
        }

        // ---- Phase 7: HP[q][jh..jh+3] = sum_k H[q][k] * PP[k][j] ----
        {
            float4 acc = make_float4(0.f, 0.f, 0.f, 0.f);
            #pragma unroll
            for (int k = 0; k < 16; ++k) {
                float hv = Hb[q7 * 20 + k];
                float4 pp = ld4(&PP[k * 20 + jh]);
                acc.x = fmaf(hv, pp.x, acc.x); acc.y = fmaf(hv, pp.y, acc.y);
                acc.z = fmaf(hv, pp.z, acc.z); acc.w = fmaf(hv, pp.w, acc.w);
            }
            st4(&HP[q7 * 20 + jh], acc);
        }
        __syncwarp();

        // ---- Phase 8: P_new = PP - K * HP  (K[i][q] = X2[q][i]); PP regs preserved ----
        {
            float n[8];
            #pragma unroll
            for (int j = 0; j < 8; ++j) n[j] = a[j];
            #pragma unroll
            for (int q = 0; q < 8; ++q) {
                float x = X2[q * 20 + row];
                float4 h0 = ld4(&HP[q * 20 + j0]);
                float4 h1 = ld4(&HP[q * 20 + j0 + 4]);
                n[0] = fmaf(-x, h0.x, n[0]); n[1] = fmaf(-x, h0.y, n[1]);
                n[2] = fmaf(-x, h0.z, n[2]); n[3] = fmaf(-x, h0.w, n[3]);
                n[4] = fmaf(-x, h1.x, n[4]); n[5] = fmaf(-x, h1.y, n[5]);
                n[6] = fmaf(-x, h1.z, n[6]); n[7] = fmaf(-x, h1.w, n[7]);
            }
            st4(&P[row * 20 + j0],     make_float4(n[0], n[1], n[2], n[3]));
            st4(&P[row * 20 + j0 + 4], make_float4(n[4], n[5], n[6], n[7]));
        }
        __syncwarp();

        // ---- Phase 9: solve PP * X = W (16x16 GJ), registers + shfl; X = G_{t-1}^T ----
        if (t > 0) {
            #pragma unroll
            for (int p = 0; p < 16; ++p) {
                const int hp = (p >= 8) ? 1 : 0;
                float cand = a[p & 7];
                float f_num = shfl(cand, (row << 1) | hp);
                float diag  = shfl(cand, (p << 1) | hp);
                const int src = (p << 1) | h;
                float pa[8], pw[8];
                #pragma unroll
                for (int j = 0; j < 8; ++j) { pa[j] = shfl(a[j], src); pw[j] = shfl(w[j], src); }
                float f = (row == p) ? 0.0f : f_num * rcpa(diag);
                #pragma unroll
                for (int j = 0; j < 8; ++j) {
                    a[j] = fmaf(-f, pa[j], a[j]);
                    w[j] = fmaf(-f, pw[j], w[j]);
                }
            }
            // own diagonal PP[row][row]
            const int ri = row & 7;
            float s01 = (ri & 1) ? a[1] : a[0];
            float s23 = (ri & 1) ? a[3] : a[2];
            float s45 = (ri & 1) ? a[5] : a[4];
            float s67 = (ri & 1) ? a[7] : a[6];
            float t0 = (ri & 2) ? s23 : s01;
            float t1 = (ri & 2) ? s67 : s45;
            float cand_r = (ri & 4) ? t1 : t0;
            float diag_r = shfl(cand_r, (row << 1) | ((row >= 8) ? 1 : 0));
            float invd = rcpa(diag_r);
            float* xo = &g_X[(((size_t)(t - 1) * BATCH + b) * 256) + row * 16 + j0];
            st4(xo,     make_float4(w[0] * invd, w[1] * invd, w[2] * invd, w[3] * invd));
            st4(xo + 4, make_float4(w[4] * invd, w[5] * invd, w[6] * invd, w[7] * invd));
        }
    }
}

__global__ __launch_bounds__(256) void kf_backward(float* __restrict__ out)
{
    const int warp = (blockIdx.x * blockDim.x + threadIdx.x) >> 5;
    const int lane = threadIdx.x & 31;
    const int b = warp;
    const int i = lane & 15;   // both half-warps duplicate -> safe shfl

    float ss = out[((size_t)b * T + (T - 1)) * NS + i];

    float xc[16];
    {
        const float* Xp = &g_X[((size_t)(T - 2) * BATCH + b) * 256];
        #pragma unroll
        for (int j = 0; j < 16; ++j) xc[j] = Xp[j * 16 + i];
    }

    #pragma unroll 1
    for (int t = T - 2; t >= 0; --t) {
        float xn[16];
        if (t > 0) {
            const float* Xn = &g_X[((size_t)(t - 1) * BATCH + b) * 256];
            #pragma unroll
            for (int j = 0; j < 16; ++j) xn[j] = Xn[j * 16 + i];
        }
        float spn = g_sp[((size_t)b * T + t + 1) * NS + i];
        float d = ss - spn;
        float acc = out[((size_t)b * T + t) * NS + i];   // s_f[t]
        #pragma unroll
        for (int j = 0; j < 16; ++j) {
            float dj = __shfl_sync(0xffffffffu, d, j, 16);
            acc = fmaf(dj, xc[j], acc);
        }
        ss = acc;
        if (lane < 16) out[((size_t)b * T + t) * NS + i] = ss;
        if (t > 0) {
            #pragma unroll
            for (int j = 0; j < 16; ++j) xc[j] = xn[j];
        }
    }
}

extern "C" void kernel_launch(void* const* d_in, const int* in_sizes, int n_in,
                              void* d_out, int out_size) {
    (void)in_sizes; (void)n_in; (void)out_size;
    const float* state0   = (const float*)d_in[0];
    const float* P0       = (const float*)d_in[1];
    const float* controls = (const float*)d_in[2];
    const float* obs      = (const float*)d_in[3];
    const float* A        = (const float*)d_in[4];
    const float* Bc       = (const float*)d_in[5];
    const float* H        = (const float*)d_in[6];
    const float* Q        = (const float*)d_in[7];
    const float* R        = (const float*)d_in[8];
    float* out = (float*)d_out;

    kf_forward<<<BATCH / WB, WB * 32>>>(state0, P0, controls, obs, A, Bc, H, Q, R, out);
    kf_backward<<<BATCH / 8, 256>>>(out);
}

// round 5
// speedup vs baseline: 6.1055x; 3.0934x over previous
#include <cuda_runtime.h>

#define BATCH 2048
#define T 128
#define NS 16
#define MS 8
#define CS 4
#define DT 0.01f

// Batch-independent gain sequences (small, L2/L1-resident) + batch states.
__device__ float g_K[T * MS * NS];              // K[t][q][i] = Kalman gain K[i][q]
__device__ float g_Pf[(T - 1) * NS * NS];       // P_f[t], t = 0..T-2
__device__ float g_Xs[(T - 1) * NS * NS];       // X[t] = G[t]^T, t = 0..T-2
__device__ float g_sp[(size_t)BATCH * T * NS];  // predicted states (t>=1 used)

__device__ __forceinline__ float4 ld4(const float* p) { return *reinterpret_cast<const float4*>(p); }
__device__ __forceinline__ void st4(float* p, float4 v) { *reinterpret_cast<float4*>(p) = v; }
__device__ __forceinline__ float rcpa(float x) { float y; asm("rcp.approx.f32 %0, %1;" : "=f"(y) : "f"(x)); return y; }
__device__ __forceinline__ float shfl(float v, int s) { return __shfl_sync(0xffffffffu, v, s); }
__device__ __forceinline__ float shflx(float v, int m) { return __shfl_xor_sync(0xffffffffu, v, m); }
__device__ __forceinline__ float shfl16(float v, int s) { return __shfl_sync(0xffffffffu, v, s, 16); }

// ============================================================================
// Kernel A: batch-independent Riccati recursion (ONE warp, serial over T).
// Computes K[t] and P_f[t] sequences.
// ============================================================================
__global__ __launch_bounds__(32) void kf_gains(
    const float* __restrict__ P0, const float* __restrict__ A,
    const float* __restrict__ H, const float* __restrict__ Q,
    const float* __restrict__ R)
{
    __shared__ float Fb[16 * 20], Ftb[16 * 20], Qb[16 * 20];
    __shared__ float Hb[8 * 20], Ht[16 * 8], Rb[64];
    __shared__ float P[16 * 20], PP[16 * 20];
    __shared__ float PHt[16 * 8], X2[8 * 20], HP[8 * 20];

    const int lane = threadIdx.x;
    for (int idx = lane; idx < 256; idx += 32) {
        int i = idx >> 4, k = idx & 15;
        float a = A[idx];
        float f = (i == k ? 1.0f : 0.0f) + DT * a;
        Fb[i * 20 + k] = f; Ftb[k * 20 + i] = f;
        Qb[i * 20 + k] = Q[idx];
        P[i * 20 + k] = P0[idx];          // batch 0's P0 (identical across batch)
    }
    for (int idx = lane; idx < 128; idx += 32) {
        int q = idx >> 4, k = idx & 15;
        float h = H[idx];
        Hb[q * 20 + k] = h; Ht[k * 8 + q] = h;
    }
    if (lane < 64) {}                     // (32 threads; loop R below)
    for (int idx = lane; idx < 64; idx += 32) Rb[idx] = R[idx];
    __syncwarp();

    const int row = lane >> 1, h = lane & 1, j0 = h * 8;
    const int rr = row & 7;
    const int q7 = lane >> 2, jh = (lane & 3) * 4;

    float frow[16];
    #pragma unroll
    for (int k = 0; k < 16; ++k) frow[k] = Fb[row * 20 + k];

    float a[8], w[8];

    for (int t = 0; t < T; ++t) {
        // Phase 1: W = F * P_f[t-1]
        #pragma unroll
        for (int j = 0; j < 8; ++j) w[j] = 0.0f;
        #pragma unroll
        for (int k = 0; k < 16; ++k) {
            float fv = frow[k];
            float4 p0 = ld4(&P[k * 20 + j0]);
            float4 p1 = ld4(&P[k * 20 + j0 + 4]);
            w[0] = fmaf(fv, p0.x, w[0]); w[1] = fmaf(fv, p0.y, w[1]);
            w[2] = fmaf(fv, p0.z, w[2]); w[3] = fmaf(fv, p0.w, w[3]);
            w[4] = fmaf(fv, p1.x, w[4]); w[5] = fmaf(fv, p1.y, w[5]);
            w[6] = fmaf(fv, p1.z, w[6]); w[7] = fmaf(fv, p1.w, w[7]);
        }

        // Phase 2: PP = W * F^T + Q
        {
            float wk[16];
            #pragma unroll
            for (int j = 0; j < 8; ++j) {
                wk[j0 + j] = w[j];
                wk[(j0 ^ 8) + j] = shflx(w[j], 1);
            }
            float4 q0 = ld4(&Qb[row * 20 + j0]);
            float4 q1 = ld4(&Qb[row * 20 + j0 + 4]);
            a[0] = q0.x; a[1] = q0.y; a[2] = q0.z; a[3] = q0.w;
            a[4] = q1.x; a[5] = q1.y; a[6] = q1.z; a[7] = q1.w;
            #pragma unroll
            for (int k = 0; k < 16; ++k) {
                float wv = wk[k];
                float4 f0 = ld4(&Ftb[k * 20 + j0]);
                float4 f1 = ld4(&Ftb[k * 20 + j0 + 4]);
                a[0] = fmaf(wv, f0.x, a[0]); a[1] = fmaf(wv, f0.y, a[1]);
                a[2] = fmaf(wv, f0.z, a[2]); a[3] = fmaf(wv, f0.w, a[3]);
                a[4] = fmaf(wv, f1.x, a[4]); a[5] = fmaf(wv, f1.y, a[5]);
                a[6] = fmaf(wv, f1.z, a[6]); a[7] = fmaf(wv, f1.w, a[7]);
            }
            st4(&PP[row * 20 + j0],     make_float4(a[0], a[1], a[2], a[3]));
            st4(&PP[row * 20 + j0 + 4], make_float4(a[4], a[5], a[6], a[7]));
        }

        // Phase 3: PHt[i][q] = sum_k PP[i][k] * H[q][k]
        {
            float pk[16];
            #pragma unroll
            for (int j = 0; j < 8; ++j) {
                pk[j0 + j] = a[j];
                pk[(j0 ^ 8) + j] = shflx(a[j], 1);
            }
            const int qh = h * 4;
            float4 acc = make_float4(0.f, 0.f, 0.f, 0.f);
            #pragma unroll
            for (int k = 0; k < 16; ++k) {
                float p = pk[k];
                float4 hv = ld4(&Ht[k * 8 + qh]);
                acc.x = fmaf(p, hv.x, acc.x); acc.y = fmaf(p, hv.y, acc.y);
                acc.z = fmaf(p, hv.z, acc.z); acc.w = fmaf(p, hv.w, acc.w);
            }
            st4(&PHt[row * 8 + qh], acc);
        }
        __syncwarp();

        // Phase 4: S rows + RHS rows into registers
        float s4[4], rhs[8];
        {
            const int ch = h * 4;
            s4[0] = Rb[rr * 8 + ch];     s4[1] = Rb[rr * 8 + ch + 1];
            s4[2] = Rb[rr * 8 + ch + 2]; s4[3] = Rb[rr * 8 + ch + 3];
            #pragma unroll
            for (int k = 0; k < 16; ++k) {
                float hv = Hb[rr * 20 + k];
                float4 ph = ld4(&PHt[k * 8 + ch]);
                s4[0] = fmaf(hv, ph.x, s4[0]); s4[1] = fmaf(hv, ph.y, s4[1]);
                s4[2] = fmaf(hv, ph.z, s4[2]); s4[3] = fmaf(hv, ph.w, s4[3]);
            }
            #pragma unroll
            for (int j = 0; j < 8; ++j)
                rhs[j] = PHt[(h * 8 + j) * 8 + rr];
        }

        // Phase 5: GJ solve S * X2 = PHt^T (8x8); store X2 (= K^T) to smem + gmem
        {
            #pragma unroll
            for (int p = 0; p < 8; ++p) {
                const int hp = (p >= 4) ? 1 : 0;
                float cand = s4[p & 3];
                float f_num = shfl(cand, (rr << 1) | hp);
                float diag  = shfl(cand, (p << 1) | hp);
                const int src = (p << 1) | h;
                float ps0 = shfl(s4[0], src), ps1 = shfl(s4[1], src);
                float ps2 = shfl(s4[2], src), ps3 = shfl(s4[3], src);
                float pr[8];
                #pragma unroll
                for (int j = 0; j < 8; ++j) pr[j] = shfl(rhs[j], src);
                float f = (rr == p) ? 0.0f : f_num * rcpa(diag);
                s4[0] = fmaf(-f, ps0, s4[0]); s4[1] = fmaf(-f, ps1, s4[1]);
                s4[2] = fmaf(-f, ps2, s4[2]); s4[3] = fmaf(-f, ps3, s4[3]);
                #pragma unroll
                for (int j = 0; j < 8; ++j) rhs[j] = fmaf(-f, pr[j], rhs[j]);
            }
            float s01 = (rr & 1) ? s4[1] : s4[0];
            float s23 = (rr & 1) ? s4[3] : s4[2];
            float cand_r = (rr & 2) ? s23 : s01;
            float diag_r = shfl(cand_r, (rr << 1) | ((rr >= 4) ? 1 : 0));
            float invd = rcpa(diag_r);
            if (lane < 16) {
                float4 x0 = make_float4(rhs[0] * invd, rhs[1] * invd, rhs[2] * invd, rhs[3] * invd);
                float4 x1 = make_float4(rhs[4] * invd, rhs[5] * invd, rhs[6] * invd, rhs[7] * invd);
                st4(&X2[rr * 20 + h * 8], x0);
                st4(&X2[rr * 20 + h * 8 + 4], x1);
                st4(&g_K[t * 128 + rr * 16 + h * 8], x0);
                st4(&g_K[t * 128 + rr * 16 + h * 8 + 4], x1);
            }
        }
        __syncwarp();

        // Phase 7: HP[q][j] = sum_k H[q][k] * PP[k][j]
        {
            float4 acc = make_float4(0.f, 0.f, 0.f, 0.f);
            #pragma unroll
            for (int k = 0; k < 16; ++k) {
                float hv = Hb[q7 * 20 + k];
                float4 pp = ld4(&PP[k * 20 + jh]);
                acc.x = fmaf(hv, pp.x, acc.x); acc.y = fmaf(hv, pp.y, acc.y);
                acc.z = fmaf(hv, pp.z, acc.z); acc.w = fmaf(hv, pp.w, acc.w);
            }
            st4(&HP[q7 * 20 + jh], acc);
        }
        __syncwarp();

        // Phase 8: P_f[t] = PP - K * HP
        {
            float n[8];
            #pragma unroll
            for (int j = 0; j < 8; ++j) n[j] = a[j];
            #pragma unroll
            for (int q = 0; q < 8; ++q) {
                float x = X2[q * 20 + row];
                float4 h0 = ld4(&HP[q * 20 + j0]);
                float4 h1 = ld4(&HP[q * 20 + j0 + 4]);
                n[0] = fmaf(-x, h0.x, n[0]); n[1] = fmaf(-x, h0.y, n[1]);
                n[2] = fmaf(-x, h0.z, n[2]); n[3] = fmaf(-x, h0.w, n[3]);
                n[4] = fmaf(-x, h1.x, n[4]); n[5] = fmaf(-x, h1.y, n[5]);
                n[6] = fmaf(-x, h1.z, n[6]); n[7] = fmaf(-x, h1.w, n[7]);
            }
            float4 v0 = make_float4(n[0], n[1], n[2], n[3]);
            float4 v1 = make_float4(n[4], n[5], n[6], n[7]);
            st4(&P[row * 20 + j0], v0);
            st4(&P[row * 20 + j0 + 4], v1);
            if (t < T - 1) {
                st4(&g_Pf[t * 256 + row * 16 + j0], v0);
                st4(&g_Pf[t * 256 + row * 16 + j0 + 4], v1);
            }
        }
        __syncwarp();
    }
}

// ============================================================================
// Kernel B: smoother gains, 127 parallel warps. X[t] = P_p[t+1]^-1 * F * P_f[t].
// ============================================================================
__global__ __launch_bounds__(32) void kf_smoother_gains(
    const float* __restrict__ A, const float* __restrict__ Q)
{
    __shared__ float Fb[16 * 20], Ftb[16 * 20], Qb[16 * 20], Pf[16 * 20];
    const int t = blockIdx.x;   // 0..T-2
    const int lane = threadIdx.x;

    for (int idx = lane; idx < 256; idx += 32) {
        int i = idx >> 4, k = idx & 15;
        float av = A[idx];
        float f = (i == k ? 1.0f : 0.0f) + DT * av;
        Fb[i * 20 + k] = f; Ftb[k * 20 + i] = f;
        Qb[i * 20 + k] = Q[idx];
        Pf[i * 20 + k] = g_Pf[t * 256 + idx];
    }
    __syncwarp();

    const int row = lane >> 1, h = lane & 1, j0 = h * 8;
    float frow[16];
    #pragma unroll
    for (int k = 0; k < 16; ++k) frow[k] = Fb[row * 20 + k];

    float a[8], w[8];
    // W = F * P_f[t]
    #pragma unroll
    for (int j = 0; j < 8; ++j) w[j] = 0.0f;
    #pragma unroll
    for (int k = 0; k < 16; ++k) {
        float fv = frow[k];
        float4 p0 = ld4(&Pf[k * 20 + j0]);
        float4 p1 = ld4(&Pf[k * 20 + j0 + 4]);
        w[0] = fmaf(fv, p0.x, w[0]); w[1] = fmaf(fv, p0.y, w[1]);
        w[2] = fmaf(fv, p0.z, w[2]); w[3] = fmaf(fv, p0.w, w[3]);
        w[4] = fmaf(fv, p1.x, w[4]); w[5] = fmaf(fv, p1.y, w[5]);
        w[6] = fmaf(fv, p1.z, w[6]); w[7] = fmaf(fv, p1.w, w[7]);
    }
    // PP = W * F^T + Q  (= P_p[t+1])
    {
        float wk[16];
        #pragma unroll
        for (int j = 0; j < 8; ++j) {
            wk[j0 + j] = w[j];
            wk[(j0 ^ 8) + j] = shflx(w[j], 1);
        }
        float4 q0 = ld4(&Qb[row * 20 + j0]);
        float4 q1 = ld4(&Qb[row * 20 + j0 + 4]);
        a[0] = q0.x; a[1] = q0.y; a[2] = q0.z; a[3] = q0.w;
        a[4] = q1.x; a[5] = q1.y; a[6] = q1.z; a[7] = q1.w;
        #pragma unroll
        for (int k = 0; k < 16; ++k) {
            float wv = wk[k];
            float4 f0 = ld4(&Ftb[k * 20 + j0]);
            float4 f1 = ld4(&Ftb[k * 20 + j0 + 4]);
            a[0] = fmaf(wv, f0.x, a[0]); a[1] = fmaf(wv, f0.y, a[1]);
            a[2] = fmaf(wv, f0.z, a[2]); a[3] = fmaf(wv, f0.w, a[3]);
            a[4] = fmaf(wv, f1.x, a[4]); a[5] = fmaf(wv, f1.y, a[5]);
            a[6] = fmaf(wv, f1.z, a[6]); a[7] = fmaf(wv, f1.w, a[7]);
        }
    }
    // GJ solve PP * X = W (16x16)
    #pragma unroll
    for (int p = 0; p < 16; ++p) {
        const int hp = (p >= 8) ? 1 : 0;
        float cand = a[p & 7];
        float f_num = shfl(cand, (row << 1) | hp);
        float diag  = shfl(cand, (p << 1) | hp);
        const int src = (p << 1) | h;
        float pa[8], pw[8];
        #pragma unroll
        for (int j = 0; j < 8; ++j) { pa[j] = shfl(a[j], src); pw[j] = shfl(w[j], src); }
        float f = (row == p) ? 0.0f : f_num * rcpa(diag);
        #pragma unroll
        for (int j = 0; j < 8; ++j) {
            a[j] = fmaf(-f, pa[j], a[j]);
            w[j] = fmaf(-f, pw[j], w[j]);
        }
    }
    const int ri = row & 7;
    float s01 = (ri & 1) ? a[1] : a[0];
    float s23 = (ri & 1) ? a[3] : a[2];
    float s45 = (ri & 1) ? a[5] : a[4];
    float s67 = (ri & 1) ? a[7] : a[6];
    float t0 = (ri & 2) ? s23 : s01;
    float t1 = (ri & 2) ? s67 : s45;
    float cand_r = (ri & 4) ? t1 : t0;
    float diag_r = shfl(cand_r, (row << 1) | ((row >= 8) ? 1 : 0));
    float invd = rcpa(diag_r);
    st4(&g_Xs[t * 256 + row * 16 + j0],
        make_float4(w[0] * invd, w[1] * invd, w[2] * invd, w[3] * invd));
    st4(&g_Xs[t * 256 + row * 16 + j0 + 4],
        make_float4(w[4] * invd, w[5] * invd, w[6] * invd, w[7] * invd));
}

// ============================================================================
// Kernel C: per-batch state filter (2 batches per warp; 16 lanes per batch).
// ============================================================================
__global__ __launch_bounds__(128) void kf_states(
    const float* __restrict__ state0, const float* __restrict__ controls,
    const float* __restrict__ obs, const float* __restrict__ A,
    const float* __restrict__ Bc, const float* __restrict__ H,
    float* __restrict__ out)
{
    const int L = threadIdx.x & 31;
    const int gw = blockIdx.x * 4 + (threadIdx.x >> 5);
    const int b = gw * 2 + (L >> 4);
    const int i = L & 15;

    float arow[16], hrow[16], brow[4];
    #pragma unroll
    for (int k = 0; k < 16; ++k) arow[k] = A[i * 16 + k];
    #pragma unroll
    for (int k = 0; k < 16; ++k) hrow[k] = H[(i & 7) * 16 + k];
    #pragma unroll
    for (int c = 0; c < 4; ++c) brow[c] = Bc[i * 4 + c];

    float s = state0[b * 16 + i];
    float u_c = (i < 4) ? controls[(size_t)b * T * 4 + i] : 0.0f;
    float y_c = (i < 8) ? obs[(size_t)b * T * 8 + i] : 0.0f;

    #pragma unroll 1
    for (int t = 0; t < T; ++t) {
        float u_n = 0.0f, y_n = 0.0f;
        if (t + 1 < T) {
            u_n = (i < 4) ? controls[((size_t)b * T + t + 1) * 4 + i] : 0.0f;
            y_n = (i < 8) ? obs[((size_t)b * T + t + 1) * 8 + i] : 0.0f;
        }
        float kq[8];
        #pragma unroll
        for (int q = 0; q < 8; ++q) kq[q] = g_K[t * 128 + q * 16 + i];

        // s_p = s + DT*(A s + Bc u)
        float a0 = 0.0f, a1 = 0.0f;
        #pragma unroll
        for (int k = 0; k < 8; ++k) {
            a0 = fmaf(arow[k], shfl16(s, k), a0);
            a1 = fmaf(arow[k + 8], shfl16(s, k + 8), a1);
        }
        #pragma unroll
        for (int c = 0; c < 4; ++c) a0 = fmaf(brow[c], shfl16(u_c, c), a0);
        float sp = s + DT * (a0 + a1);
        if (t > 0) g_sp[((size_t)b * T + t) * NS + i] = sp;

        // innov = y - H s_p
        float h0 = 0.0f, h1 = 0.0f;
        #pragma unroll
        for (int k = 0; k < 8; ++k) {
            h0 = fmaf(hrow[k], shfl16(sp, k), h0);
            h1 = fmaf(hrow[k + 8], shfl16(sp, k + 8), h1);
        }
        float iv = y_c - (h0 + h1);

        // s = s_p + K innov
        float acc = sp;
        #pragma unroll
        for (int q = 0; q < 8; ++q) acc = fmaf(kq[q], shfl16(iv, q), acc);
        s = acc;
        out[((size_t)b * T + t) * NS + i] = s;
        u_c = u_n; y_c = y_n;
    }
}

// ============================================================================
// Kernel D: backward smoother. X[t] shared across batch (L1/L2-hot).
// ============================================================================
__global__ __launch_bounds__(128) void kf_backward(float* __restrict__ out)
{
    const int L = threadIdx.x & 31;
    const int gw = blockIdx.x * 4 + (threadIdx.x >> 5);
    const int b = gw * 2 + (L >> 4);
    const int i = L & 15;

    float ss = out[((size_t)b * T + (T - 1)) * NS + i];
    float xc[16];
    #pragma unroll
    for (int j = 0; j < 16; ++j) xc[j] = g_Xs[(T - 2) * 256 + j * 16 + i];
    float spn_c = g_sp[((size_t)b * T + (T - 1)) * NS + i];
    float sf_c  = out[((size_t)b * T + (T - 2)) * NS + i];

    #pragma unroll 1
    for (int t = T - 2; t >= 0; --t) {
        float xn[16]; float spn_n = 0.0f, sf_n = 0.0f;
        if (t > 0) {
            #pragma unroll
            for (int j = 0; j < 16; ++j) xn[j] = g_Xs[(t - 1) * 256 + j * 16 + i];
            spn_n = g_sp[((size_t)b * T + t) * NS + i];
            sf_n  = out[((size_t)b * T + t - 1) * NS + i];
        }
        float d = ss - spn_c;
        float a0 = 0.0f, a1 = 0.0f;
        #pragma unroll
        for (int j = 0; j < 8; ++j) {
            a0 = fmaf(shfl16(d, j), xc[j], a0);
            a1 = fmaf(shfl16(d, j + 8), xc[j + 8], a1);
        }
        ss = sf_c + a0 + a1;
        out[((size_t)b * T + t) * NS + i] = ss;
        if (t > 0) {
            #pragma unroll
            for (int j = 0; j < 16; ++j) xc[j] = xn[j];
            spn_c = spn_n; sf_c = sf_n;
        }
    }
}

extern "C" void kernel_launch(void* const* d_in, const int* in_sizes, int n_in,
                              void* d_out, int out_size) {
    (void)in_sizes; (void)n_in; (void)out_size;
    const float* state0   = (const float*)d_in[0];
    const float* P0       = (const float*)d_in[1];
    const float* controls = (const float*)d_in[2];
    const float* obs      = (const float*)d_in[3];
    const float* A        = (const float*)d_in[4];
    const float* Bc       = (const float*)d_in[5];
    const float* H        = (const float*)d_in[6];
    const float* Q        = (const float*)d_in[7];
    const float* R        = (const float*)d_in[8];
    float* out = (float*)d_out;

    kf_gains<<<1, 32>>>(P0, A, H, Q, R);
    kf_smoother_gains<<<T - 1, 32>>>(A, Q);
    kf_states<<<BATCH / 8, 128>>>(state0, controls, obs, A, Bc, H, out);
    kf_backward<<<BATCH / 8, 128>>>(out);
}

// round 6
// speedup vs baseline: 7.6450x; 1.2521x over previous
#include <cuda_runtime.h>

#define BATCH 2048
#define T 128
#define NS 16
#define MS 8
#define CS 4
#define DT 0.01f
#define SB 16   // batches per block in states/backward

// Batch-independent gain sequences (small, L2-resident).
__device__ float g_K[T * MS * NS];              // K[t][q][i] = Kalman gain K[i][q]
__device__ float g_Pf[(T - 1) * NS * NS];       // P_f[t], t = 0..T-2
__device__ float g_Xs[(T - 1) * NS * NS];       // X[t] = G[t]^T, t = 0..T-2

__device__ __forceinline__ float4 ld4(const float* p) { return *reinterpret_cast<const float4*>(p); }
__device__ __forceinline__ void st4(float* p, float4 v) { *reinterpret_cast<float4*>(p) = v; }
__device__ __forceinline__ float rcpa(float x) { float y; asm("rcp.approx.f32 %0, %1;" : "=f"(y) : "f"(x)); return y; }
__device__ __forceinline__ float shfl(float v, int s) { return __shfl_sync(0xffffffffu, v, s); }
__device__ __forceinline__ float shflx(float v, int m) { return __shfl_xor_sync(0xffffffffu, v, m); }
__device__ __forceinline__ float shfl16(float v, int s) { return __shfl_sync(0xffffffffu, v, s, 16); }

// ============================================================================
// Kernel A: batch-independent Riccati recursion (ONE warp, serial over T).
// ============================================================================
__global__ __launch_bounds__(32) void kf_gains(
    const float* __restrict__ P0, const float* __restrict__ A,
    const float* __restrict__ H, const float* __restrict__ Q,
    const float* __restrict__ R)
{
    __shared__ float Fb[16 * 20], Ftb[16 * 20], Qb[16 * 20];
    __shared__ float Hb[8 * 20], Ht[16 * 8], Rb[64];
    __shared__ float P[16 * 20], PHt[16 * 8], X2[8 * 20];

    const int lane = threadIdx.x;
    for (int idx = lane; idx < 256; idx += 32) {
        int i = idx >> 4, k = idx & 15;
        float a = A[idx];
        float f = (i == k ? 1.0f : 0.0f) + DT * a;
        Fb[i * 20 + k] = f; Ftb[k * 20 + i] = f;
        Qb[i * 20 + k] = Q[idx];
        P[i * 20 + k] = P0[idx];
    }
    for (int idx = lane; idx < 128; idx += 32) {
        int q = idx >> 4, k = idx & 15;
        float h = H[idx];
        Hb[q * 20 + k] = h; Ht[k * 8 + q] = h;
    }
    for (int idx = lane; idx < 64; idx += 32) Rb[idx] = R[idx];
    __syncwarp();

    const int row = lane >> 1, h = lane & 1, j0 = h * 8;
    const int rr = row & 7;

    float frow[16];
    #pragma unroll
    for (int k = 0; k < 16; ++k) frow[k] = Fb[row * 20 + k];

    float a[8], w[8];

    for (int t = 0; t < T; ++t) {
        // Phase 1: W = F * P
        #pragma unroll
        for (int j = 0; j < 8; ++j) w[j] = 0.0f;
        #pragma unroll
        for (int k = 0; k < 16; ++k) {
            float fv = frow[k];
            float4 p0 = ld4(&P[k * 20 + j0]);
            float4 p1 = ld4(&P[k * 20 + j0 + 4]);
            w[0] = fmaf(fv, p0.x, w[0]); w[1] = fmaf(fv, p0.y, w[1]);
            w[2] = fmaf(fv, p0.z, w[2]); w[3] = fmaf(fv, p0.w, w[3]);
            w[4] = fmaf(fv, p1.x, w[4]); w[5] = fmaf(fv, p1.y, w[5]);
            w[6] = fmaf(fv, p1.z, w[6]); w[7] = fmaf(fv, p1.w, w[7]);
        }

        // Phase 2: PP = W * F^T + Q  (kept in regs a[])
        {
            float wk[16];
            #pragma unroll
            for (int j = 0; j < 8; ++j) {
                wk[j0 + j] = w[j];
                wk[(j0 ^ 8) + j] = shflx(w[j], 1);
            }
            float4 q0 = ld4(&Qb[row * 20 + j0]);
            float4 q1 = ld4(&Qb[row * 20 + j0 + 4]);
            a[0] = q0.x; a[1] = q0.y; a[2] = q0.z; a[3] = q0.w;
            a[4] = q1.x; a[5] = q1.y; a[6] = q1.z; a[7] = q1.w;
            #pragma unroll
            for (int k = 0; k < 16; ++k) {
                float wv = wk[k];
                float4 f0 = ld4(&Ftb[k * 20 + j0]);
                float4 f1 = ld4(&Ftb[k * 20 + j0 + 4]);
                a[0] = fmaf(wv, f0.x, a[0]); a[1] = fmaf(wv, f0.y, a[1]);
                a[2] = fmaf(wv, f0.z, a[2]); a[3] = fmaf(wv, f0.w, a[3]);
                a[4] = fmaf(wv, f1.x, a[4]); a[5] = fmaf(wv, f1.y, a[5]);
                a[6] = fmaf(wv, f1.z, a[6]); a[7] = fmaf(wv, f1.w, a[7]);
            }
        }

        // Phase 3: PHt[i][q] = sum_k PP[i][k] * H[q][k]
        {
            float pk[16];
            #pragma unroll
            for (int j = 0; j < 8; ++j) {
                pk[j0 + j] = a[j];
                pk[(j0 ^ 8) + j] = shflx(a[j], 1);
            }
            const int qh = h * 4;
            float4 acc = make_float4(0.f, 0.f, 0.f, 0.f);
            #pragma unroll
            for (int k = 0; k < 16; ++k) {
                float p = pk[k];
                float4 hv = ld4(&Ht[k * 8 + qh]);
                acc.x = fmaf(p, hv.x, acc.x); acc.y = fmaf(p, hv.y, acc.y);
                acc.z = fmaf(p, hv.z, acc.z); acc.w = fmaf(p, hv.w, acc.w);
            }
            st4(&PHt[row * 8 + qh], acc);
        }
        __syncwarp();

        // Phase 4: S rows + RHS rows into registers
        float s4[4], rhs[8];
        {
            const int ch = h * 4;
            s4[0] = Rb[rr * 8 + ch];     s4[1] = Rb[rr * 8 + ch + 1];
            s4[2] = Rb[rr * 8 + ch + 2]; s4[3] = Rb[rr * 8 + ch + 3];
            #pragma unroll
            for (int k = 0; k < 16; ++k) {
                float hv = Hb[rr * 20 + k];
                float4 ph = ld4(&PHt[k * 8 + ch]);
                s4[0] = fmaf(hv, ph.x, s4[0]); s4[1] = fmaf(hv, ph.y, s4[1]);
                s4[2] = fmaf(hv, ph.z, s4[2]); s4[3] = fmaf(hv, ph.w, s4[3]);
            }
            #pragma unroll
            for (int j = 0; j < 8; ++j)
                rhs[j] = PHt[(h * 8 + j) * 8 + rr];
        }

        // Phase 5: GJ solve S * X2 = PHt^T (8x8); X2 = K^T
        {
            #pragma unroll
            for (int p = 0; p < 8; ++p) {
                const int hp = (p >= 4) ? 1 : 0;
                float cand = s4[p & 3];
                float f_num = shfl(cand, (rr << 1) | hp);
                float diag  = shfl(cand, (p << 1) | hp);
                const int src = (p << 1) | h;
                float ps0 = shfl(s4[0], src), ps1 = shfl(s4[1], src);
                float ps2 = shfl(s4[2], src), ps3 = shfl(s4[3], src);
                float pr[8];
                #pragma unroll
                for (int j = 0; j < 8; ++j) pr[j] = shfl(rhs[j], src);
                float f = (rr == p) ? 0.0f : f_num * rcpa(diag);
                s4[0] = fmaf(-f, ps0, s4[0]); s4[1] = fmaf(-f, ps1, s4[1]);
                s4[2] = fmaf(-f, ps2, s4[2]); s4[3] = fmaf(-f, ps3, s4[3]);
                #pragma unroll
                for (int j = 0; j < 8; ++j) rhs[j] = fmaf(-f, pr[j], rhs[j]);
            }
            float s01 = (rr & 1) ? s4[1] : s4[0];
            float s23 = (rr & 1) ? s4[3] : s4[2];
            float cand_r = (rr & 2) ? s23 : s01;
            float diag_r = shfl(cand_r, (rr << 1) | ((rr >= 4) ? 1 : 0));
            float invd = rcpa(diag_r);
            if (lane < 16) {
                float4 x0 = make_float4(rhs[0] * invd, rhs[1] * invd, rhs[2] * invd, rhs[3] * invd);
                float4 x1 = make_float4(rhs[4] * invd, rhs[5] * invd, rhs[6] * invd, rhs[7] * invd);
                st4(&X2[rr * 20 + h * 8], x0);
                st4(&X2[rr * 20 + h * 8 + 4], x1);
                st4(&g_K[t * 128 + rr * 16 + h * 8], x0);
                st4(&g_K[t * 128 + rr * 16 + h * 8 + 4], x1);
            }
        }
        __syncwarp();

        // Phase 8: P_f = PP - K * (H*PP).  PP symmetric => (H*PP)[q][j] = PHt[j][q].
        {
            float n[8];
            #pragma unroll
            for (int j = 0; j < 8; ++j) n[j] = a[j];
            #pragma unroll
            for (int q = 0; q < 8; ++q) {
                float x = X2[q * 20 + row];           // K[row][q]
                #pragma unroll
                for (int j = 0; j < 8; ++j)
                    n[j] = fmaf(-x, PHt[(j0 + j) * 8 + q], n[j]);
            }
            float4 v0 = make_float4(n[0], n[1], n[2], n[3]);
            float4 v1 = make_float4(n[4], n[5], n[6], n[7]);
            st4(&P[row * 20 + j0], v0);
            st4(&P[row * 20 + j0 + 4], v1);
            if (t < T - 1) {
                st4(&g_Pf[t * 256 + row * 16 + j0], v0);
                st4(&g_Pf[t * 256 + row * 16 + j0 + 4], v1);
            }
        }
        __syncwarp();
    }
}

// ============================================================================
// Kernel B: smoother gains, T-1 parallel warps. X[t] = P_p[t+1]^-1 * F * P_f[t].
// ============================================================================
__global__ __launch_bounds__(32) void kf_smoother_gains(
    const float* __restrict__ A, const float* __restrict__ Q)
{
    __shared__ float Fb[16 * 20], Ftb[16 * 20], Qb[16 * 20], Pf[16 * 20];
    const int t = blockIdx.x;
    const int lane = threadIdx.x;

    for (int idx = lane; idx < 256; idx += 32) {
        int i = idx >> 4, k = idx & 15;
        float av = A[idx];
        float f = (i == k ? 1.0f : 0.0f) + DT * av;
        Fb[i * 20 + k] = f; Ftb[k * 20 + i] = f;
        Qb[i * 20 + k] = Q[idx];
        Pf[i * 20 + k] = g_Pf[t * 256 + idx];
    }
    __syncwarp();

    const int row = lane >> 1, h = lane & 1, j0 = h * 8;
    float frow[16];
    #pragma unroll
    for (int k = 0; k < 16; ++k) frow[k] = Fb[row * 20 + k];

    float a[8], w[8];
    #pragma unroll
    for (int j = 0; j < 8; ++j) w[j] = 0.0f;
    #pragma unroll
    for (int k = 0; k < 16; ++k) {
        float fv = frow[k];
        float4 p0 = ld4(&Pf[k * 20 + j0]);
        float4 p1 = ld4(&Pf[k * 20 + j0 + 4]);
        w[0] = fmaf(fv, p0.x, w[0]); w[1] = fmaf(fv, p0.y, w[1]);
        w[2] = fmaf(fv, p0.z, w[2]); w[3] = fmaf(fv, p0.w, w[3]);
        w[4] = fmaf(fv, p1.x, w[4]); w[5] = fmaf(fv, p1.y, w[5]);
        w[6] = fmaf(fv, p1.z, w[6]); w[7] = fmaf(fv, p1.w, w[7]);
    }
    {
        float wk[16];
        #pragma unroll
        for (int j = 0; j < 8; ++j) {
            wk[j0 + j] = w[j];
            wk[(j0 ^ 8) + j] = shflx(w[j], 1);
        }
        float4 q0 = ld4(&Qb[row * 20 + j0]);
        float4 q1 = ld4(&Qb[row * 20 + j0 + 4]);
        a[0] = q0.x; a[1] = q0.y; a[2] = q0.z; a[3] = q0.w;
        a[4] = q1.x; a[5] = q1.y; a[6] = q1.z; a[7] = q1.w;
        #pragma unroll
        for (int k = 0; k < 16; ++k) {
            float wv = wk[k];
            float4 f0 = ld4(&Ftb[k * 20 + j0]);
            float4 f1 = ld4(&Ftb[k * 20 + j0 + 4]);
            a[0] = fmaf(wv, f0.x, a[0]); a[1] = fmaf(wv, f0.y, a[1]);
            a[2] = fmaf(wv, f0.z, a[2]); a[3] = fmaf(wv, f0.w, a[3]);
            a[4] = fmaf(wv, f1.x, a[4]); a[5] = fmaf(wv, f1.y, a[5]);
            a[6] = fmaf(wv, f1.z, a[6]); a[7] = fmaf(wv, f1.w, a[7]);
        }
    }
    #pragma unroll
    for (int p = 0; p < 16; ++p) {
        const int hp = (p >= 8) ? 1 : 0;
        float cand = a[p & 7];
        float f_num = shfl(cand, (row << 1) | hp);
        float diag  = shfl(cand, (p << 1) | hp);
        const int src = (p << 1) | h;
        float pa[8], pw[8];
        #pragma unroll
        for (int j = 0; j < 8; ++j) { pa[j] = shfl(a[j], src); pw[j] = shfl(w[j], src); }
        float f = (row == p) ? 0.0f : f_num * rcpa(diag);
        #pragma unroll
        for (int j = 0; j < 8; ++j) {
            a[j] = fmaf(-f, pa[j], a[j]);
            w[j] = fmaf(-f, pw[j], w[j]);
        }
    }
    const int ri = row & 7;
    float s01 = (ri & 1) ? a[1] : a[0];
    float s23 = (ri & 1) ? a[3] : a[2];
    float s45 = (ri & 1) ? a[5] : a[4];
    float s67 = (ri & 1) ? a[7] : a[6];
    float t0 = (ri & 2) ? s23 : s01;
    float t1 = (ri & 2) ? s67 : s45;
    float cand_r = (ri & 4) ? t1 : t0;
    float diag_r = shfl(cand_r, (row << 1) | ((row >= 8) ? 1 : 0));
    float invd = rcpa(diag_r);
    st4(&g_Xs[t * 256 + row * 16 + j0],
        make_float4(w[0] * invd, w[1] * invd, w[2] * invd, w[3] * invd));
    st4(&g_Xs[t * 256 + row * 16 + j0 + 4],
        make_float4(w[4] * invd, w[5] * invd, w[6] * invd, w[7] * invd));
}

// ============================================================================
// Kernel C: per-batch forward state filter. K/u/y staged in smem.
// ============================================================================
__global__ __launch_bounds__(256) void kf_states(
    const float* __restrict__ state0, const float* __restrict__ controls,
    const float* __restrict__ obs, const float* __restrict__ A,
    const float* __restrict__ Bc, const float* __restrict__ H,
    float* __restrict__ out)
{
    extern __shared__ float sm[];
    float* Ks = sm;                        // T*128 = 16384 floats
    float* us = Ks + T * 128;              // SB*T*4 = 8192 floats
    float* ys = us + SB * T * 4;           // SB*T*8 = 16384 floats

    const int tid = threadIdx.x;
    const int b0 = blockIdx.x * SB;

    for (int idx = tid; idx < 4096; idx += 256)
        st4(&Ks[idx * 4], ld4(&g_K[idx * 4]));
    {
        const float* src = controls + (size_t)b0 * T * 4;
        for (int idx = tid; idx < 2048; idx += 256)
            st4(&us[idx * 4], ld4(&src[idx * 4]));
    }
    {
        const float* src = obs + (size_t)b0 * T * 8;
        for (int idx = tid; idx < 4096; idx += 256)
            st4(&ys[idx * 4], ld4(&src[idx * 4]));
    }
    __syncthreads();

    const int L = tid & 31;
    const int bl = (tid >> 5) * 2 + (L >> 4);
    const int b = b0 + bl;
    const int i = L & 15;

    float arow[16], hrow[16], brow[4];
    #pragma unroll
    for (int k = 0; k < 16; ++k) arow[k] = A[i * 16 + k];
    #pragma unroll
    for (int k = 0; k < 16; ++k) hrow[k] = H[(i & 7) * 16 + k];
    #pragma unroll
    for (int c = 0; c < 4; ++c) brow[c] = Bc[i * 4 + c];

    float s = state0[b * 16 + i];

    #pragma unroll 1
    for (int t = 0; t < T; ++t) {
        // s_p = s + DT*(A s + Bc u_t)
        float a0 = 0.0f, a1 = 0.0f;
        #pragma unroll
        for (int k = 0; k < 8; ++k) {
            a0 = fmaf(arow[k], shfl16(s, k), a0);
            a1 = fmaf(arow[k + 8], shfl16(s, k + 8), a1);
        }
        #pragma unroll
        for (int c = 0; c < 4; ++c) a0 = fmaf(brow[c], us[bl * 512 + t * 4 + c], a0);
        float sp = s + DT * (a0 + a1);

        // innov = y - H s_p  (lanes i<8 meaningful)
        float h0 = 0.0f, h1 = 0.0f;
        #pragma unroll
        for (int k = 0; k < 8; ++k) {
            h0 = fmaf(hrow[k], shfl16(sp, k), h0);
            h1 = fmaf(hrow[k + 8], shfl16(sp, k + 8), h1);
        }
        float iv = ys[bl * 1024 + t * 8 + (i & 7)] - (h0 + h1);

        // s = s_p + K innov
        float acc = sp;
        #pragma unroll
        for (int q = 0; q < 8; ++q)
            acc = fmaf(Ks[t * 128 + q * 16 + i], shfl16(iv, q), acc);
        s = acc;
        out[((size_t)b * T + t) * NS + i] = s;
    }
}

// ============================================================================
// Kernel D: backward smoother. Xs/u staged in smem; s_p recomputed from s_f.
// ============================================================================
__global__ __launch_bounds__(256) void kf_backward(
    const float* __restrict__ controls, const float* __restrict__ A,
    const float* __restrict__ Bc, float* __restrict__ out)
{
    extern __shared__ float sm[];
    float* Xs = sm;                        // (T-1)*256 = 32512 floats
    float* us = Xs + (T - 1) * 256;        // SB*T*4 = 8192 floats

    const int tid = threadIdx.x;
    const int b0 = blockIdx.x * SB;

    for (int idx = tid; idx < 8128; idx += 256)
        st4(&Xs[idx * 4], ld4(&g_Xs[idx * 4]));
    {
        const float* src = controls + (size_t)b0 * T * 4;
        for (int idx = tid; idx < 2048; idx += 256)
            st4(&us[idx * 4], ld4(&src[idx * 4]));
    }
    __syncthreads();

    const int L = tid & 31;
    const int bl = (tid >> 5) * 2 + (L >> 4);
    const int b = b0 + bl;
    const int i = L & 15;

    float arow[16], brow[4];
    #pragma unroll
    for (int k = 0; k < 16; ++k) arow[k] = A[i * 16 + k];
    #pragma unroll
    for (int c = 0; c < 4; ++c) brow[c] = Bc[i * 4 + c];

    float ss   = out[((size_t)b * T + (T - 1)) * NS + i];
    float sf_c = out[((size_t)b * T + (T - 2)) * NS + i];

    #pragma unroll 1
    for (int t = T - 2; t >= 0; --t) {
        float sf_n = 0.0f;
        if (t > 0) sf_n = out[((size_t)b * T + t - 1) * NS + i];

        // s_p[t+1] = sf_c + DT*(A sf_c + Bc u[t+1])
        float a0 = 0.0f, a1 = 0.0f;
        #pragma unroll
        for (int k = 0; k < 8; ++k) {
            a0 = fmaf(arow[k], shfl16(sf_c, k), a0);
            a1 = fmaf(arow[k + 8], shfl16(sf_c, k + 8), a1);
        }
        #pragma unroll
        for (int c = 0; c < 4; ++c) a0 = fmaf(brow[c], us[bl * 512 + (t + 1) * 4 + c], a0);
        float sp = sf_c + DT * (a0 + a1);

        float d = ss - sp;
        float m0 = 0.0f, m1 = 0.0f;
        #pragma unroll
        for (int j = 0; j < 8; ++j) {
            m0 = fmaf(shfl16(d, j), Xs[t * 256 + j * 16 + i], m0);
            m1 = fmaf(shfl16(d, j + 8), Xs[t * 256 + (j + 8) * 16 + i], m1);
        }
        ss = sf_c + m0 + m1;
        out[((size_t)b * T + t) * NS + i] = ss;
        sf_c = sf_n;
    }
}

extern "C" void kernel_launch(void* const* d_in, const int* in_sizes, int n_in,
                              void* d_out, int out_size) {
    (void)in_sizes; (void)n_in; (void)out_size;
    const float* state0   = (const float*)d_in[0];
    const float* P0       = (const float*)d_in[1];
    const float* controls = (const float*)d_in[2];
    const float* obs      = (const float*)d_in[3];
    const float* A        = (const float*)d_in[4];
    const float* Bc       = (const float*)d_in[5];
    const float* H        = (const float*)d_in[6];
    const float* Q        = (const float*)d_in[7];
    const float* R        = (const float*)d_in[8];
    float* out = (float*)d_out;

    const int smem_states   = (T * 128 + SB * T * 4 + SB * T * 8) * 4;   // 163840 B
    const int smem_backward = ((T - 1) * 256 + SB * T * 4) * 4;          // 162816 B
    cudaFuncSetAttribute(kf_states,   cudaFuncAttributeMaxDynamicSharedMemorySize, smem_states);
    cudaFuncSetAttribute(kf_backward, cudaFuncAttributeMaxDynamicSharedMemorySize, smem_backward);

    kf_gains<<<1, 32>>>(P0, A, H, Q, R);
    kf_smoother_gains<<<T - 1, 32>>>(A, Q);
    kf_states<<<BATCH / SB, 256, smem_states>>>(state0, controls, obs, A, Bc, H, out);
    kf_backward<<<BATCH / SB, 256, smem_backward>>>(controls, A, Bc, out);
}